// round 2
// baseline (speedup 1.0000x reference)
#include <cuda_runtime.h>
#include <math_constants.h>

// RoIPool: input (N=2, C=256, H=50, W=50) f32, rois (K, 5) f32
// output (K, C, 7, 7) f32. spatial_scale = 0.0625, P = 7.
//
// One thread per output element, thread index == output linear index
// (pw fastest) so stores are fully coalesced. Bin bounds replicate the
// JAX reference exactly: rintf (round-half-even) for coords, floor/ceil
// bin edges clipped to [0, H]/[0, W], empty bins -> 0.

#define P 7
#define C_DIM 256
#define H_DIM 50
#define W_DIM 50
#define SCALE 0.0625f

__global__ void roipool_kernel(const float* __restrict__ x,
                               const float* __restrict__ rois,
                               float* __restrict__ out,
                               int total)
{
    int idx = blockIdx.x * blockDim.x + threadIdx.x;
    if (idx >= total) return;

    int pw = idx % P;
    int ph = (idx / P) % P;
    int c  = (idx / (P * P)) % C_DIM;
    int k  = idx / (P * P * C_DIM);

    const float* r = rois + k * 5;
    int   b  = (int)r[0];
    float x1 = rintf(r[1] * SCALE);
    float y1 = rintf(r[2] * SCALE);
    float x2 = rintf(r[3] * SCALE);
    float y2 = rintf(r[4] * SCALE);

    float roi_w = fmaxf(x2 - x1 + 1.0f, 1.0f);
    float roi_h = fmaxf(y2 - y1 + 1.0f, 1.0f);
    float bin_w = roi_w * (1.0f / P);
    float bin_h = roi_h * (1.0f / P);

    float hs_f = fminf(fmaxf(floorf((float)ph * bin_h) + y1, 0.0f), (float)H_DIM);
    float he_f = fminf(fmaxf(ceilf(((float)ph + 1.0f) * bin_h) + y1, 0.0f), (float)H_DIM);
    float ws_f = fminf(fmaxf(floorf((float)pw * bin_w) + x1, 0.0f), (float)W_DIM);
    float we_f = fminf(fmaxf(ceilf(((float)pw + 1.0f) * bin_w) + x1, 0.0f), (float)W_DIM);

    int hs = (int)hs_f;
    int he = (int)he_f;
    int ws = (int)ws_f;
    int we = (int)we_f;

    float m = 0.0f;  // empty bins produce 0
    if (he > hs && we > ws) {
        m = -CUDART_INF_F;
        const float* base = x + ((size_t)b * C_DIM + c) * (H_DIM * W_DIM);
        for (int h = hs; h < he; ++h) {
            const float* row = base + h * W_DIM;
            for (int w = ws; w < we; ++w) {
                m = fmaxf(m, row[w]);
            }
        }
    }
    out[idx] = m;
}

extern "C" void kernel_launch(void* const* d_in, const int* in_sizes, int n_in,
                              void* d_out, int out_size)
{
    const float* x    = (const float*)d_in[0];
    const float* rois = (const float*)d_in[1];
    float* out        = (float*)d_out;

    int total = out_size;  // K * C * 7 * 7
    int threads = 256;
    int blocks = (total + threads - 1) / threads;
    roipool_kernel<<<blocks, threads>>>(x, rois, out, total);
}